// round 2
// baseline (speedup 1.0000x reference)
#include <cuda_runtime.h>
#include <cstdint>

// ---------------- problem dims ----------------
#define IN_F   2048
#define OUT_F  2048
#define BATCH  8192
#define GDIM   8

// ---------------- GEMM config -----------------
#define BM      128
#define BN      128
#define BK      32
#define STAGES  4
#define THREADS 256
#define NCHUNKS (IN_F / BK)        // 64
#define PITCH   36                 // floats per smem row (bank-conflict-free)
#define TILE_F  (BM * PITCH)       // 4608 floats per tile (BM == BN)
#define STAGE_F (3 * TILE_F)       // x | W | gsum
#define SMEM_BYTES (STAGES * STAGE_F * 4)   // 221184

// ---------------- device scratch ----------------
__device__ float g_gsumT[(size_t)OUT_F * IN_F];  // tf32-rounded, [o][i]
__device__ float g_partials[4096];
__device__ float g_mean;

// ---------------- helpers ----------------
__device__ __forceinline__ uint32_t smem_u32(const void* p) {
    uint32_t a;
    asm("{ .reg .u64 t; cvta.to.shared.u64 t, %1; cvt.u32.u64 %0, t; }"
        : "=r"(a) : "l"(p));
    return a;
}

__device__ __forceinline__ uint32_t f2tf32(float v) {
    uint32_t r;
    asm("cvt.rna.tf32.f32 %0, %1;" : "=r"(r) : "f"(v));
    return r;
}

__device__ __forceinline__ void cp16(uint32_t dst, const float* src) {
    asm volatile("cp.async.cg.shared.global [%0], [%1], 16;"
                 :: "r"(dst), "l"(src));
}
#define CP_COMMIT() asm volatile("cp.async.commit_group;" ::: "memory")
#define CP_WAIT2()  asm volatile("cp.async.wait_group 2;" ::: "memory")

__device__ __forceinline__ void mma_tf32(float* c,
                                         uint32_t a0, uint32_t a1, uint32_t a2, uint32_t a3,
                                         uint32_t b0, uint32_t b1) {
    asm volatile(
        "mma.sync.aligned.m16n8k8.row.col.f32.tf32.tf32.f32 "
        "{%0,%1,%2,%3}, {%4,%5,%6,%7}, {%8,%9}, {%0,%1,%2,%3};"
        : "+f"(c[0]), "+f"(c[1]), "+f"(c[2]), "+f"(c[3])
        : "r"(a0), "r"(a1), "r"(a2), "r"(a3), "r"(b0), "r"(b1));
}

// ---------------- kernel 1: grid reduce + transpose + partial sums ----------------
__global__ void __launch_bounds__(1024) k_prep(const float* __restrict__ grid) {
    __shared__ float tile[32][33];
    __shared__ float red[1024];
    int tx = threadIdx.x, ty = threadIdx.y;
    int i = blockIdx.y * 32 + ty;   // in-feature
    int o = blockIdx.x * 32 + tx;   // out-feature
    const float4* p = reinterpret_cast<const float4*>(grid + ((size_t)i * OUT_F + o) * GDIM);
    float4 a = p[0], b = p[1];
    float s = ((a.x + a.y) + (a.z + a.w)) + ((b.x + b.y) + (b.z + b.w));
    tile[ty][tx] = s;
    int t = ty * 32 + tx;
    red[t] = s;
    __syncthreads();
    #pragma unroll
    for (int off = 512; off > 0; off >>= 1) {
        if (t < off) red[t] += red[t + off];
        __syncthreads();
    }
    if (t == 0) g_partials[blockIdx.y * gridDim.x + blockIdx.x] = red[0];
    // transposed tf32-rounded write: gsumT[o][i]
    float v = tile[tx][ty];
    int oo = blockIdx.x * 32 + ty;
    int ii = blockIdx.y * 32 + tx;
    reinterpret_cast<uint32_t*>(g_gsumT)[(size_t)oo * IN_F + ii] = f2tf32(v);
}

// ---------------- kernel 2: final mean ----------------
__global__ void __launch_bounds__(1024) k_mean() {
    __shared__ float red[1024];
    int t = threadIdx.x;
    red[t] = g_partials[t] + g_partials[t + 1024] + g_partials[t + 2048] + g_partials[t + 3072];
    __syncthreads();
    #pragma unroll
    for (int off = 512; off > 0; off >>= 1) {
        if (t < off) red[t] += red[t + off];
        __syncthreads();
    }
    if (t == 0) g_mean = red[0] * (1.0f / ((float)IN_F * (float)OUT_F * (float)GDIM));
}

// ---------------- kernel 3: fused GEMM (mma.sync tf32) ----------------
// out[m][n] = sum_k x[m][k]*w1[n][k] + sum_k exp(-(x[m][k]-mean)^2)*gsumT[n][k]
__global__ void __launch_bounds__(THREADS, 1)
k_gemm(const float* __restrict__ x, const float* __restrict__ w1,
       float* __restrict__ out) {
    extern __shared__ float smem[];
    const uint32_t sbase = smem_u32(smem);
    const int tid  = threadIdx.x;
    const int warp = tid >> 5;
    const int lane = tid & 31;
    const int grp  = lane >> 2;   // 0..7
    const int tig  = lane & 3;    // 0..3
    const int warp_m = warp >> 2; // 0..1  (64-row slab)
    const int warp_n = warp & 3;  // 0..3  (32-col slab)

    const int m0 = blockIdx.y * BM;
    const int n0 = blockIdx.x * BN;
    const float gmean = g_mean;

    const float* xg = x  + (size_t)m0 * IN_F;
    const float* wg = w1 + (size_t)n0 * IN_F;
    const float* gg = g_gsumT + (size_t)n0 * IN_F;

    float acc[4][4][4];
    #pragma unroll
    for (int mi = 0; mi < 4; ++mi)
        #pragma unroll
        for (int ni = 0; ni < 4; ++ni)
            #pragma unroll
            for (int j = 0; j < 4; ++j) acc[mi][ni][j] = 0.f;

    // loader indices: 1024 16B-chunks per tile, 4 per thread
    const int lrow0 = tid >> 3;       // +32 per i-step? no: c = tid + i*256 -> row = c>>3
    const int lch   = tid & 7;

    auto issue_stage = [&](int kc) {
        const int s = kc & (STAGES - 1);
        const uint32_t stx = sbase + (uint32_t)(s * STAGE_F) * 4u;
        const uint32_t stw = stx + TILE_F * 4u;
        const uint32_t stg = stw + TILE_F * 4u;
        const int k0 = kc * BK;
        #pragma unroll
        for (int i = 0; i < 4; ++i) {
            const int r = lrow0 + i * 32;             // (tid + i*256) >> 3
            const uint32_t doff = (uint32_t)(r * PITCH + lch * 4) * 4u;
            cp16(stx + doff, xg + (size_t)r * IN_F + k0 + lch * 4);
            cp16(stw + doff, wg + (size_t)r * IN_F + k0 + lch * 4);
            cp16(stg + doff, gg + (size_t)r * IN_F + k0 + lch * 4);
        }
        CP_COMMIT();
    };

    // prologue
    issue_stage(0);
    issue_stage(1);
    issue_stage(2);

    #pragma unroll 1
    for (int kc = 0; kc < NCHUNKS; ++kc) {
        CP_WAIT2();
        __syncthreads();

        if (kc + 3 < NCHUNKS) issue_stage(kc + 3);
        else CP_COMMIT();   // keep group accounting uniform

        const int s = kc & (STAGES - 1);
        const float* sx = smem + s * STAGE_F;
        const float* sw = sx + TILE_F;
        const float* sg = sw + TILE_F;

        #pragma unroll
        for (int ks = 0; ks < 4; ++ks) {
            const int kk = ks * 8;

            // A fragments (x) + basis fragments, 4 m-subtiles
            uint32_t ax[4][4], ab[4][4];
            #pragma unroll
            for (int mi = 0; mi < 4; ++mi) {
                const int r = warp_m * 64 + mi * 16 + grp;
                float f0 = sx[r * PITCH + kk + tig];
                float f1 = sx[(r + 8) * PITCH + kk + tig];
                float f2 = sx[r * PITCH + kk + tig + 4];
                float f3 = sx[(r + 8) * PITCH + kk + tig + 4];
                ax[mi][0] = f2tf32(f0); ax[mi][1] = f2tf32(f1);
                ax[mi][2] = f2tf32(f2); ax[mi][3] = f2tf32(f3);
                float d0 = f0 - gmean, d1 = f1 - gmean, d2 = f2 - gmean, d3 = f3 - gmean;
                ab[mi][0] = f2tf32(__expf(-d0 * d0));
                ab[mi][1] = f2tf32(__expf(-d1 * d1));
                ab[mi][2] = f2tf32(__expf(-d2 * d2));
                ab[mi][3] = f2tf32(__expf(-d3 * d3));
            }

            // B fragments (W tf32-converted, gsum pre-rounded), 4 n-subtiles
            uint32_t bw[4][2], bg[4][2];
            #pragma unroll
            for (int ni = 0; ni < 4; ++ni) {
                const int nr = warp_n * 32 + ni * 8 + grp;
                bw[ni][0] = f2tf32(sw[nr * PITCH + kk + tig]);
                bw[ni][1] = f2tf32(sw[nr * PITCH + kk + tig + 4]);
                bg[ni][0] = __float_as_uint(sg[nr * PITCH + kk + tig]);
                bg[ni][1] = __float_as_uint(sg[nr * PITCH + kk + tig + 4]);
            }

            #pragma unroll
            for (int mi = 0; mi < 4; ++mi)
                #pragma unroll
                for (int ni = 0; ni < 4; ++ni) {
                    mma_tf32(acc[mi][ni], ax[mi][0], ax[mi][1], ax[mi][2], ax[mi][3],
                             bw[ni][0], bw[ni][1]);
                    mma_tf32(acc[mi][ni], ab[mi][0], ab[mi][1], ab[mi][2], ab[mi][3],
                             bg[ni][0], bg[ni][1]);
                }
        }
        __syncthreads();
    }

    // ---- epilogue: direct float2 stores ----
    #pragma unroll
    for (int mi = 0; mi < 4; ++mi) {
        const int r = m0 + warp_m * 64 + mi * 16 + grp;
        #pragma unroll
        for (int ni = 0; ni < 4; ++ni) {
            const int c = n0 + warp_n * 32 + ni * 8 + tig * 2;
            float2 v0 = make_float2(acc[mi][ni][0], acc[mi][ni][1]);
            float2 v1 = make_float2(acc[mi][ni][2], acc[mi][ni][3]);
            *reinterpret_cast<float2*>(out + (size_t)r * OUT_F + c) = v0;
            *reinterpret_cast<float2*>(out + (size_t)(r + 8) * OUT_F + c) = v1;
        }
    }
}

// ---------------- launch ----------------
extern "C" void kernel_launch(void* const* d_in, const int* in_sizes, int n_in,
                              void* d_out, int out_size) {
    const float* x    = (const float*)d_in[0];
    const float* w1   = (const float*)d_in[1];
    const float* grid = (const float*)d_in[2];
    float* out = (float*)d_out;

    k_prep<<<dim3(OUT_F / 32, IN_F / 32), dim3(32, 32)>>>(grid);
    k_mean<<<1, 1024>>>();

    cudaFuncSetAttribute(k_gemm, cudaFuncAttributeMaxDynamicSharedMemorySize, SMEM_BYTES);
    k_gemm<<<dim3(OUT_F / BN, BATCH / BM), THREADS, SMEM_BYTES>>>(x, w1, out);
}

// round 3
// speedup vs baseline: 1.1201x; 1.1201x over previous
#include <cuda_runtime.h>
#include <cstdint>

// ---------------- problem dims ----------------
#define IN_F   2048
#define OUT_F  2048
#define BATCH  8192
#define GDIM   8
#define KTOT   (2 * IN_F)          // 4096 concat K

// ---------------- GEMM config -----------------
#define BM      128
#define BN      128
#define BK      32
#define STAGES  5
#define THREADS 256
#define NCHUNKS (KTOT / BK)        // 128
#define PITCH   36                 // floats per smem row (bank-conflict-free)
#define TILE_F  (BM * PITCH)       // 4608 floats (BM == BN)
#define STAGE_F (2 * TILE_F)       // A | B
#define SMEM_BYTES (STAGES * STAGE_F * 4)   // 184320

// ---------------- device scratch ----------------
__device__ float g_acat[(size_t)BATCH * KTOT];   // [b][ x_tf32 | basis_tf32 ]
__device__ float g_bcat[(size_t)OUT_F * KTOT];   // [n][ w1_tf32 | gsumT_tf32 ]
__device__ float g_partials[4096];
__device__ float g_mean;

// ---------------- helpers ----------------
__device__ __forceinline__ uint32_t smem_u32(const void* p) {
    uint32_t a;
    asm("{ .reg .u64 t; cvta.to.shared.u64 t, %1; cvt.u32.u64 %0, t; }"
        : "=r"(a) : "l"(p));
    return a;
}

__device__ __forceinline__ uint32_t f2tf32(float v) {
    uint32_t r;
    asm("cvt.rna.tf32.f32 %0, %1;" : "=r"(r) : "f"(v));
    return r;
}

__device__ __forceinline__ void cp16(uint32_t dst, const float* src) {
    asm volatile("cp.async.cg.shared.global [%0], [%1], 16;"
                 :: "r"(dst), "l"(src));
}
#define CP_COMMIT() asm volatile("cp.async.commit_group;" ::: "memory")
#define CP_WAIT3()  asm volatile("cp.async.wait_group 3;" ::: "memory")

__device__ __forceinline__ void mma_tf32(float* c,
                                         uint32_t a0, uint32_t a1, uint32_t a2, uint32_t a3,
                                         uint32_t b0, uint32_t b1) {
    asm volatile(
        "mma.sync.aligned.m16n8k8.row.col.f32.tf32.tf32.f32 "
        "{%0,%1,%2,%3}, {%4,%5,%6,%7}, {%8,%9}, {%0,%1,%2,%3};"
        : "+f"(c[0]), "+f"(c[1]), "+f"(c[2]), "+f"(c[3])
        : "r"(a0), "r"(a1), "r"(a2), "r"(a3), "r"(b0), "r"(b1));
}

// ---------------- kernel 1: grid reduce + transpose into g_bcat + partials ----
__global__ void __launch_bounds__(1024) k_prep(const float* __restrict__ grid) {
    __shared__ float tile[32][33];
    __shared__ float red[1024];
    int tx = threadIdx.x, ty = threadIdx.y;
    int i = blockIdx.y * 32 + ty;   // in-feature
    int o = blockIdx.x * 32 + tx;   // out-feature
    const float4* p = reinterpret_cast<const float4*>(grid + ((size_t)i * OUT_F + o) * GDIM);
    float4 a = p[0], b = p[1];
    float s = ((a.x + a.y) + (a.z + a.w)) + ((b.x + b.y) + (b.z + b.w));
    tile[ty][tx] = s;
    int t = ty * 32 + tx;
    red[t] = s;
    __syncthreads();
    #pragma unroll
    for (int off = 512; off > 0; off >>= 1) {
        if (t < off) red[t] += red[t + off];
        __syncthreads();
    }
    if (t == 0) g_partials[blockIdx.y * gridDim.x + blockIdx.x] = red[0];
    // transposed tf32-rounded write into concat-B upper half: bcat[o][2048 + i]
    float v = tile[tx][ty];
    int oo = blockIdx.x * 32 + ty;
    int ii = blockIdx.y * 32 + tx;
    reinterpret_cast<uint32_t*>(g_bcat)[(size_t)oo * KTOT + IN_F + ii] = f2tf32(v);
}

// ---------------- kernel 2: final mean ----------------
__global__ void __launch_bounds__(1024) k_mean() {
    __shared__ float red[1024];
    int t = threadIdx.x;
    red[t] = g_partials[t] + g_partials[t + 1024] + g_partials[t + 2048] + g_partials[t + 3072];
    __syncthreads();
    #pragma unroll
    for (int off = 512; off > 0; off >>= 1) {
        if (t < off) red[t] += red[t + off];
        __syncthreads();
    }
    if (t == 0) g_mean = red[0] * (1.0f / ((float)IN_F * (float)OUT_F * (float)GDIM));
}

// ---------------- kernel 3: w1 -> tf32 into g_bcat lower half ----------------
__global__ void __launch_bounds__(256) k_wcvt(const float* __restrict__ w1) {
    size_t idx = (size_t)blockIdx.x * 256 + threadIdx.x;   // float4 index
    const float4 f = reinterpret_cast<const float4*>(w1)[idx];
    size_t n = idx / (IN_F / 4);
    size_t k4 = idx % (IN_F / 4);
    uint4 u = make_uint4(f2tf32(f.x), f2tf32(f.y), f2tf32(f.z), f2tf32(f.w));
    *reinterpret_cast<uint4*>(
        reinterpret_cast<uint32_t*>(g_bcat) + n * KTOT + k4 * 4) = u;
}

// ---------------- kernel 4: x -> tf32 + basis -> g_acat ----------------
__global__ void __launch_bounds__(256) k_xbasis(const float* __restrict__ x) {
    const float gmean = g_mean;
    size_t idx = (size_t)blockIdx.x * 256 + threadIdx.x;   // float4 index
    const float4 f = reinterpret_cast<const float4*>(x)[idx];
    size_t b = idx / (IN_F / 4);
    size_t k4 = idx % (IN_F / 4);
    uint32_t* dst = reinterpret_cast<uint32_t*>(g_acat) + b * KTOT;
    *reinterpret_cast<uint4*>(dst + k4 * 4) =
        make_uint4(f2tf32(f.x), f2tf32(f.y), f2tf32(f.z), f2tf32(f.w));
    float d0 = f.x - gmean, d1 = f.y - gmean, d2 = f.z - gmean, d3 = f.w - gmean;
    *reinterpret_cast<uint4*>(dst + IN_F + k4 * 4) =
        make_uint4(f2tf32(__expf(-d0 * d0)), f2tf32(__expf(-d1 * d1)),
                   f2tf32(__expf(-d2 * d2)), f2tf32(__expf(-d3 * d3)));
}

// ---------------- kernel 5: plain tf32 GEMM, K = 4096 ----------------
// out[m][n] = sum_k acat[m][k] * bcat[n][k]
__global__ void __launch_bounds__(THREADS, 1)
k_gemm(float* __restrict__ out) {
    extern __shared__ float smem[];
    const uint32_t sbase = smem_u32(smem);
    const int tid  = threadIdx.x;
    const int warp = tid >> 5;
    const int lane = tid & 31;
    const int grp  = lane >> 2;   // 0..7
    const int tig  = lane & 3;    // 0..3
    const int warp_m = warp >> 2; // 0..1  (64-row slab)
    const int warp_n = warp & 3;  // 0..3  (32-col slab)

    const int m0 = blockIdx.y * BM;
    const int n0 = blockIdx.x * BN;

    const float* ag = g_acat + (size_t)m0 * KTOT;
    const float* bg = g_bcat + (size_t)n0 * KTOT;

    float acc[4][4][4];
    #pragma unroll
    for (int mi = 0; mi < 4; ++mi)
        #pragma unroll
        for (int ni = 0; ni < 4; ++ni)
            #pragma unroll
            for (int j = 0; j < 4; ++j) acc[mi][ni][j] = 0.f;

    // loader: 2048 16B-chunks per stage (A:1024, B:1024), 8 per thread
    const int lrow = tid >> 3;        // 0..31, +32 per i-step
    const int lch  = tid & 7;         // 16B chunk within 128B row-slice

    auto issue_stage = [&](int kc) {
        const int s = kc & 7;                       // stage index helper
        const int st = kc % STAGES;
        (void)s;
        const uint32_t stA = sbase + (uint32_t)(st * STAGE_F) * 4u;
        const uint32_t stB = stA + TILE_F * 4u;
        const int k0 = kc * BK;
        #pragma unroll
        for (int i = 0; i < 4; ++i) {
            const int r = lrow + i * 32;
            const uint32_t doff = (uint32_t)(r * PITCH + lch * 4) * 4u;
            cp16(stA + doff, ag + (size_t)r * KTOT + k0 + lch * 4);
            cp16(stB + doff, bg + (size_t)r * KTOT + k0 + lch * 4);
        }
        CP_COMMIT();
    };

    // prologue: 4 stages in flight
    issue_stage(0);
    issue_stage(1);
    issue_stage(2);
    issue_stage(3);

    #pragma unroll 1
    for (int kc = 0; kc < NCHUNKS; ++kc) {
        CP_WAIT3();
        __syncthreads();

        if (kc + 4 < NCHUNKS) issue_stage(kc + 4);
        else CP_COMMIT();   // keep group accounting uniform

        const int st = kc % STAGES;
        const uint32_t* sa = reinterpret_cast<const uint32_t*>(smem + st * STAGE_F);
        const uint32_t* sb = sa + TILE_F;

        #pragma unroll
        for (int ks = 0; ks < 4; ++ks) {
            const int kk = ks * 8;

            uint32_t a[4][4];
            #pragma unroll
            for (int mi = 0; mi < 4; ++mi) {
                const int r = warp_m * 64 + mi * 16 + grp;
                a[mi][0] = sa[r * PITCH + kk + tig];
                a[mi][1] = sa[(r + 8) * PITCH + kk + tig];
                a[mi][2] = sa[r * PITCH + kk + tig + 4];
                a[mi][3] = sa[(r + 8) * PITCH + kk + tig + 4];
            }
            uint32_t b[4][2];
            #pragma unroll
            for (int ni = 0; ni < 4; ++ni) {
                const int nr = warp_n * 32 + ni * 8 + grp;
                b[ni][0] = sb[nr * PITCH + kk + tig];
                b[ni][1] = sb[nr * PITCH + kk + tig + 4];
            }
            #pragma unroll
            for (int mi = 0; mi < 4; ++mi)
                #pragma unroll
                for (int ni = 0; ni < 4; ++ni)
                    mma_tf32(acc[mi][ni], a[mi][0], a[mi][1], a[mi][2], a[mi][3],
                             b[ni][0], b[ni][1]);
        }
        __syncthreads();
    }

    // ---- epilogue: direct float2 stores ----
    #pragma unroll
    for (int mi = 0; mi < 4; ++mi) {
        const int r = m0 + warp_m * 64 + mi * 16 + grp;
        #pragma unroll
        for (int ni = 0; ni < 4; ++ni) {
            const int c = n0 + warp_n * 32 + ni * 8 + tig * 2;
            float2 v0 = make_float2(acc[mi][ni][0], acc[mi][ni][1]);
            float2 v1 = make_float2(acc[mi][ni][2], acc[mi][ni][3]);
            *reinterpret_cast<float2*>(out + (size_t)r * OUT_F + c) = v0;
            *reinterpret_cast<float2*>(out + (size_t)(r + 8) * OUT_F + c) = v1;
        }
    }
}

// ---------------- launch ----------------
extern "C" void kernel_launch(void* const* d_in, const int* in_sizes, int n_in,
                              void* d_out, int out_size) {
    const float* x    = (const float*)d_in[0];
    const float* w1   = (const float*)d_in[1];
    const float* grid = (const float*)d_in[2];
    float* out = (float*)d_out;

    k_prep<<<dim3(OUT_F / 32, IN_F / 32), dim3(32, 32)>>>(grid);
    k_mean<<<1, 1024>>>();
    k_wcvt<<<(OUT_F * IN_F / 4) / 256, 256>>>(w1);
    k_xbasis<<<(BATCH * IN_F / 4) / 256, 256>>>(x);

    cudaFuncSetAttribute(k_gemm, cudaFuncAttributeMaxDynamicSharedMemorySize, SMEM_BYTES);
    k_gemm<<<dim3(OUT_F / BN, BATCH / BM), THREADS, SMEM_BYTES>>>(out);
}

// round 4
// speedup vs baseline: 1.1819x; 1.0552x over previous
#include <cuda_runtime.h>
#include <cstdint>

// ---------------- problem dims ----------------
#define IN_F   2048
#define OUT_F  2048
#define BATCH  8192
#define GDIM   8
#define KTOT   (2 * IN_F)          // 4096 concat K

// ---------------- GEMM config -----------------
#define BM      128
#define BN      256
#define BK      32
#define STAGES  4
#define THREADS 256
#define NCHUNKS (KTOT / BK)        // 128
#define PITCH   36                 // floats per smem row (conflict-free)
#define TILEA_F (BM * PITCH)       // 4608 floats
#define TILEB_F (BN * PITCH)       // 9216 floats
#define STAGE_F (TILEA_F + TILEB_F)
#define SMEM_BYTES (STAGES * STAGE_F * 4)   // 221184

// ---------------- device scratch ----------------
__device__ float g_acat[(size_t)BATCH * KTOT];   // [b][ x_tf32 | basis_tf32 ]
__device__ float g_bcat[(size_t)OUT_F * KTOT];   // [n][ w1_tf32 | gsumT_tf32 ]
__device__ float g_partials[4096];
__device__ float g_mean;

// ---------------- helpers ----------------
__device__ __forceinline__ uint32_t smem_u32(const void* p) {
    uint32_t a;
    asm("{ .reg .u64 t; cvta.to.shared.u64 t, %1; cvt.u32.u64 %0, t; }"
        : "=r"(a) : "l"(p));
    return a;
}

__device__ __forceinline__ uint32_t f2tf32(float v) {
    uint32_t r;
    asm("cvt.rna.tf32.f32 %0, %1;" : "=r"(r) : "f"(v));
    return r;
}

__device__ __forceinline__ void cp16(uint32_t dst, const float* src) {
    asm volatile("cp.async.cg.shared.global [%0], [%1], 16;"
                 :: "r"(dst), "l"(src));
}
#define CP_COMMIT() asm volatile("cp.async.commit_group;" ::: "memory")
#define CP_WAIT2()  asm volatile("cp.async.wait_group 2;" ::: "memory")

__device__ __forceinline__ void mma_tf32(float* c,
                                         uint32_t a0, uint32_t a1, uint32_t a2, uint32_t a3,
                                         uint32_t b0, uint32_t b1) {
    asm volatile(
        "mma.sync.aligned.m16n8k8.row.col.f32.tf32.tf32.f32 "
        "{%0,%1,%2,%3}, {%4,%5,%6,%7}, {%8,%9}, {%0,%1,%2,%3};"
        : "+f"(c[0]), "+f"(c[1]), "+f"(c[2]), "+f"(c[3])
        : "r"(a0), "r"(a1), "r"(a2), "r"(a3), "r"(b0), "r"(b1));
}

// ---------------- kernel 1: grid reduce + transpose into g_bcat + partials ----
__global__ void __launch_bounds__(1024) k_prep(const float* __restrict__ grid) {
    __shared__ float tile[32][33];
    __shared__ float wsum[32];
    int tx = threadIdx.x, ty = threadIdx.y;
    int i = blockIdx.y * 32 + ty;   // in-feature
    int o = blockIdx.x * 32 + tx;   // out-feature
    const float4* p = reinterpret_cast<const float4*>(grid + ((size_t)i * OUT_F + o) * GDIM);
    float4 a = p[0], b = p[1];
    float s = ((a.x + a.y) + (a.z + a.w)) + ((b.x + b.y) + (b.z + b.w));
    tile[ty][tx] = s;
    // warp shuffle reduce (each row ty is one warp)
    float r = s;
    #pragma unroll
    for (int off = 16; off > 0; off >>= 1)
        r += __shfl_xor_sync(0xFFFFFFFFu, r, off);
    if (tx == 0) wsum[ty] = r;
    __syncthreads();
    if (ty == 0) {
        float w = wsum[tx];
        #pragma unroll
        for (int off = 16; off > 0; off >>= 1)
            w += __shfl_xor_sync(0xFFFFFFFFu, w, off);
        if (tx == 0) g_partials[blockIdx.y * gridDim.x + blockIdx.x] = w;
    }
    // transposed tf32-rounded write into concat-B upper half: bcat[o][2048 + i]
    float v = tile[tx][ty];
    int oo = blockIdx.x * 32 + ty;
    int ii = blockIdx.y * 32 + tx;
    reinterpret_cast<uint32_t*>(g_bcat)[(size_t)oo * KTOT + IN_F + ii] = f2tf32(v);
}

// ---------------- kernel 2: final mean ----------------
__global__ void __launch_bounds__(1024) k_mean() {
    __shared__ float red[1024];
    int t = threadIdx.x;
    red[t] = g_partials[t] + g_partials[t + 1024] + g_partials[t + 2048] + g_partials[t + 3072];
    __syncthreads();
    #pragma unroll
    for (int off = 512; off > 0; off >>= 1) {
        if (t < off) red[t] += red[t + off];
        __syncthreads();
    }
    if (t == 0) g_mean = red[0] * (1.0f / ((float)IN_F * (float)OUT_F * (float)GDIM));
}

// ---------------- kernel 3: w1 -> tf32 into g_bcat lower half ----------------
__global__ void __launch_bounds__(256) k_wcvt(const float* __restrict__ w1) {
    size_t idx = (size_t)blockIdx.x * 256 + threadIdx.x;   // float4 index
    const float4 f = reinterpret_cast<const float4*>(w1)[idx];
    size_t n = idx / (IN_F / 4);
    size_t k4 = idx % (IN_F / 4);
    uint4 u = make_uint4(f2tf32(f.x), f2tf32(f.y), f2tf32(f.z), f2tf32(f.w));
    *reinterpret_cast<uint4*>(
        reinterpret_cast<uint32_t*>(g_bcat) + n * KTOT + k4 * 4) = u;
}

// ---------------- kernel 4: x -> tf32 + basis -> g_acat ----------------
__global__ void __launch_bounds__(256) k_xbasis(const float* __restrict__ x) {
    const float gmean = g_mean;
    size_t idx = (size_t)blockIdx.x * 256 + threadIdx.x;   // float4 index
    const float4 f = reinterpret_cast<const float4*>(x)[idx];
    size_t b = idx / (IN_F / 4);
    size_t k4 = idx % (IN_F / 4);
    uint32_t* dst = reinterpret_cast<uint32_t*>(g_acat) + b * KTOT;
    *reinterpret_cast<uint4*>(dst + k4 * 4) =
        make_uint4(f2tf32(f.x), f2tf32(f.y), f2tf32(f.z), f2tf32(f.w));
    float d0 = f.x - gmean, d1 = f.y - gmean, d2 = f.z - gmean, d3 = f.w - gmean;
    *reinterpret_cast<uint4*>(dst + IN_F + k4 * 4) =
        make_uint4(f2tf32(__expf(-d0 * d0)), f2tf32(__expf(-d1 * d1)),
                   f2tf32(__expf(-d2 * d2)), f2tf32(__expf(-d3 * d3)));
}

// ---------------- kernel 5: plain tf32 GEMM, K = 4096, CTA 128x256 ----------
// out[m][n] = sum_k acat[m][k] * bcat[n][k]
__global__ void __launch_bounds__(THREADS, 1)
k_gemm(float* __restrict__ out) {
    extern __shared__ float smem[];
    const uint32_t sbase = smem_u32(smem);
    const int tid  = threadIdx.x;
    const int warp = tid >> 5;
    const int lane = tid & 31;
    const int grp  = lane >> 2;   // 0..7
    const int tig  = lane & 3;    // 0..3
    const int warp_m = warp >> 2; // 0..1  (64-row slab)
    const int warp_n = warp & 3;  // 0..3  (64-col slab)

    const int m0 = blockIdx.y * BM;
    const int n0 = blockIdx.x * BN;

    const float* ag = g_acat + (size_t)m0 * KTOT;
    const float* bg = g_bcat + (size_t)n0 * KTOT;

    float acc[4][8][4];
    #pragma unroll
    for (int mi = 0; mi < 4; ++mi)
        #pragma unroll
        for (int ni = 0; ni < 8; ++ni)
            #pragma unroll
            for (int j = 0; j < 4; ++j) acc[mi][ni][j] = 0.f;

    // loader: A = 1024 16B-chunks (4/thread), B = 2048 (8/thread)
    const int lrow = tid >> 3;        // 0..31, +32 per step
    const int lch  = tid & 7;         // 16B chunk within 128B row-slice

    auto issue_stage = [&](int kc) {
        const int st = kc & (STAGES - 1);
        const uint32_t stA = sbase + (uint32_t)(st * STAGE_F) * 4u;
        const uint32_t stB = stA + TILEA_F * 4u;
        const int k0 = kc * BK;
        #pragma unroll
        for (int i = 0; i < 4; ++i) {
            const int r = lrow + i * 32;
            const uint32_t doff = (uint32_t)(r * PITCH + lch * 4) * 4u;
            cp16(stA + doff, ag + (size_t)r * KTOT + k0 + lch * 4);
        }
        #pragma unroll
        for (int i = 0; i < 8; ++i) {
            const int r = lrow + i * 32;
            const uint32_t doff = (uint32_t)(r * PITCH + lch * 4) * 4u;
            cp16(stB + doff, bg + (size_t)r * KTOT + k0 + lch * 4);
        }
        CP_COMMIT();
    };

    // prologue: 3 stages in flight
    issue_stage(0);
    issue_stage(1);
    issue_stage(2);

    #pragma unroll 1
    for (int kc = 0; kc < NCHUNKS; ++kc) {
        CP_WAIT2();
        __syncthreads();

        if (kc + 3 < NCHUNKS) issue_stage(kc + 3);
        else CP_COMMIT();   // keep group accounting uniform

        const int st = kc & (STAGES - 1);
        const uint32_t* sa = reinterpret_cast<const uint32_t*>(smem + st * STAGE_F);
        const uint32_t* sb = sa + TILEA_F;

        #pragma unroll
        for (int ks = 0; ks < 4; ++ks) {
            const int kk = ks * 8;

            uint32_t a[4][4];
            #pragma unroll
            for (int mi = 0; mi < 4; ++mi) {
                const int r = warp_m * 64 + mi * 16 + grp;
                a[mi][0] = sa[r * PITCH + kk + tig];
                a[mi][1] = sa[(r + 8) * PITCH + kk + tig];
                a[mi][2] = sa[r * PITCH + kk + tig + 4];
                a[mi][3] = sa[(r + 8) * PITCH + kk + tig + 4];
            }
            uint32_t b[8][2];
            #pragma unroll
            for (int ni = 0; ni < 8; ++ni) {
                const int nr = warp_n * 64 + ni * 8 + grp;
                b[ni][0] = sb[nr * PITCH + kk + tig];
                b[ni][1] = sb[nr * PITCH + kk + tig + 4];
            }
            #pragma unroll
            for (int mi = 0; mi < 4; ++mi)
                #pragma unroll
                for (int ni = 0; ni < 8; ++ni)
                    mma_tf32(acc[mi][ni], a[mi][0], a[mi][1], a[mi][2], a[mi][3],
                             b[ni][0], b[ni][1]);
        }
        __syncthreads();
    }

    // ---- epilogue: direct float2 stores ----
    #pragma unroll
    for (int mi = 0; mi < 4; ++mi) {
        const int r = m0 + warp_m * 64 + mi * 16 + grp;
        #pragma unroll
        for (int ni = 0; ni < 8; ++ni) {
            const int c = n0 + warp_n * 64 + ni * 8 + tig * 2;
            float2 v0 = make_float2(acc[mi][ni][0], acc[mi][ni][1]);
            float2 v1 = make_float2(acc[mi][ni][2], acc[mi][ni][3]);
            *reinterpret_cast<float2*>(out + (size_t)r * OUT_F + c) = v0;
            *reinterpret_cast<float2*>(out + (size_t)(r + 8) * OUT_F + c) = v1;
        }
    }
}

// ---------------- launch ----------------
extern "C" void kernel_launch(void* const* d_in, const int* in_sizes, int n_in,
                              void* d_out, int out_size) {
    const float* x    = (const float*)d_in[0];
    const float* w1   = (const float*)d_in[1];
    const float* grid = (const float*)d_in[2];
    float* out = (float*)d_out;

    k_prep<<<dim3(OUT_F / 32, IN_F / 32), dim3(32, 32)>>>(grid);
    k_mean<<<1, 1024>>>();
    k_wcvt<<<(OUT_F * IN_F / 4) / 256, 256>>>(w1);
    k_xbasis<<<(BATCH * IN_F / 4) / 256, 256>>>(x);

    cudaFuncSetAttribute(k_gemm, cudaFuncAttributeMaxDynamicSharedMemorySize, SMEM_BYTES);
    k_gemm<<<dim3(OUT_F / BN, BATCH / BM), THREADS, SMEM_BYTES>>>(out);
}

// round 6
// speedup vs baseline: 1.8643x; 1.5773x over previous
#include <cuda_runtime.h>
#include <cuda_fp16.h>
#include <cstdint>

// ---------------- problem dims ----------------
#define IN_F   2048
#define OUT_F  2048
#define BATCH  8192
#define GDIM   8
#define KTOT   (2 * IN_F)          // 4096 concat K

// ---------------- GEMM config -----------------
#define BM      128
#define BN      256
#define BK      32                 // halves per chunk
#define STAGES  6
#define THREADS 256
#define NCHUNKS (KTOT / BK)        // 128
#define PITCH_B 80                 // bytes per smem row (40 halves, conflict-free)
#define TILEA_B (BM * PITCH_B)     // 10240 B
#define TILEB_B (BN * PITCH_B)     // 20480 B
#define STAGE_B (TILEA_B + TILEB_B)            // 30720 B
#define SMEM_BYTES (STAGES * STAGE_B)          // 184320

// ---------------- device scratch ----------------
__device__ __half g_acat[(size_t)BATCH * KTOT];  // [b][ x | basis ] fp16
__device__ __half g_bcat[(size_t)OUT_F * KTOT];  // [n][ w1 | gsumT ] fp16
__device__ float g_partials[4096];
__device__ float g_mean;

// ---------------- helpers ----------------
__device__ __forceinline__ uint32_t smem_u32(const void* p) {
    uint32_t a;
    asm("{ .reg .u64 t; cvta.to.shared.u64 t, %1; cvt.u32.u64 %0, t; }"
        : "=r"(a) : "l"(p));
    return a;
}

__device__ __forceinline__ void cp16(uint32_t dst, const void* src) {
    asm volatile("cp.async.cg.shared.global [%0], [%1], 16;"
                 :: "r"(dst), "l"(src));
}
#define CP_COMMIT() asm volatile("cp.async.commit_group;" ::: "memory")
#define CP_WAIT4()  asm volatile("cp.async.wait_group 4;" ::: "memory")

__device__ __forceinline__ void ldsm_x4(uint32_t& r0, uint32_t& r1,
                                        uint32_t& r2, uint32_t& r3, uint32_t addr) {
    asm volatile("ldmatrix.sync.aligned.m8n8.x4.shared.b16 {%0,%1,%2,%3}, [%4];"
                 : "=r"(r0), "=r"(r1), "=r"(r2), "=r"(r3) : "r"(addr));
}

__device__ __forceinline__ void mma_f16(float* c,
                                        uint32_t a0, uint32_t a1, uint32_t a2, uint32_t a3,
                                        uint32_t b0, uint32_t b1) {
    asm volatile(
        "mma.sync.aligned.m16n8k16.row.col.f32.f16.f16.f32 "
        "{%0,%1,%2,%3}, {%4,%5,%6,%7}, {%8,%9}, {%0,%1,%2,%3};"
        : "+f"(c[0]), "+f"(c[1]), "+f"(c[2]), "+f"(c[3])
        : "r"(a0), "r"(a1), "r"(a2), "r"(a3), "r"(b0), "r"(b1));
}

// ---------------- kernel 1: grid reduce + transpose into g_bcat + partials ----
__global__ void __launch_bounds__(1024) k_prep(const float* __restrict__ grid) {
    __shared__ float tile[32][33];
    __shared__ float wsum[32];
    int tx = threadIdx.x, ty = threadIdx.y;
    int i = blockIdx.y * 32 + ty;   // in-feature
    int o = blockIdx.x * 32 + tx;   // out-feature
    const float4* p = reinterpret_cast<const float4*>(grid + ((size_t)i * OUT_F + o) * GDIM);
    float4 a = p[0], b = p[1];
    float s = ((a.x + a.y) + (a.z + a.w)) + ((b.x + b.y) + (b.z + b.w));
    tile[ty][tx] = s;
    float r = s;
    #pragma unroll
    for (int off = 16; off > 0; off >>= 1)
        r += __shfl_xor_sync(0xFFFFFFFFu, r, off);
    if (tx == 0) wsum[ty] = r;
    __syncthreads();
    if (ty == 0) {
        float w = wsum[tx];
        #pragma unroll
        for (int off = 16; off > 0; off >>= 1)
            w += __shfl_xor_sync(0xFFFFFFFFu, w, off);
        if (tx == 0) g_partials[blockIdx.y * gridDim.x + blockIdx.x] = w;
    }
    // transposed fp16 write into concat-B upper half: bcat[o][2048 + i]
    float v = tile[tx][ty];
    int oo = blockIdx.x * 32 + ty;
    int ii = blockIdx.y * 32 + tx;
    g_bcat[(size_t)oo * KTOT + IN_F + ii] = __float2half_rn(v);
}

// ---------------- kernel 2: final mean ----------------
__global__ void __launch_bounds__(1024) k_mean() {
    __shared__ float red[1024];
    int t = threadIdx.x;
    red[t] = g_partials[t] + g_partials[t + 1024] + g_partials[t + 2048] + g_partials[t + 3072];
    __syncthreads();
    #pragma unroll
    for (int off = 512; off > 0; off >>= 1) {
        if (t < off) red[t] += red[t + off];
        __syncthreads();
    }
    if (t == 0) g_mean = red[0] * (1.0f / ((float)IN_F * (float)OUT_F * (float)GDIM));
}

// ---------------- kernel 3: w1 -> fp16 into g_bcat lower half ----------------
__global__ void __launch_bounds__(256) k_wcvt(const float* __restrict__ w1) {
    size_t idx = (size_t)blockIdx.x * 256 + threadIdx.x;   // float4 index
    const float4 f = reinterpret_cast<const float4*>(w1)[idx];
    size_t n = idx / (IN_F / 4);
    size_t k4 = idx % (IN_F / 4);
    __half2 h0 = make_half2(__float2half_rn(f.x), __float2half_rn(f.y));
    __half2 h1 = make_half2(__float2half_rn(f.z), __float2half_rn(f.w));
    *reinterpret_cast<__half2*>(g_bcat + n * KTOT + k4 * 4)     = h0;
    *reinterpret_cast<__half2*>(g_bcat + n * KTOT + k4 * 4 + 2) = h1;
}

// ---------------- kernel 4: x -> fp16 + basis -> g_acat ----------------
__global__ void __launch_bounds__(256) k_xbasis(const float* __restrict__ x) {
    const float gmean = g_mean;
    size_t idx = (size_t)blockIdx.x * 256 + threadIdx.x;   // float4 index
    const float4 f = reinterpret_cast<const float4*>(x)[idx];
    size_t b = idx / (IN_F / 4);
    size_t k4 = idx % (IN_F / 4);
    __half* dst = g_acat + b * KTOT;
    *reinterpret_cast<__half2*>(dst + k4 * 4) =
        make_half2(__float2half_rn(f.x), __float2half_rn(f.y));
    *reinterpret_cast<__half2*>(dst + k4 * 4 + 2) =
        make_half2(__float2half_rn(f.z), __float2half_rn(f.w));
    float d0 = f.x - gmean, d1 = f.y - gmean, d2 = f.z - gmean, d3 = f.w - gmean;
    *reinterpret_cast<__half2*>(dst + IN_F + k4 * 4) =
        make_half2(__float2half_rn(__expf(-d0 * d0)), __float2half_rn(__expf(-d1 * d1)));
    *reinterpret_cast<__half2*>(dst + IN_F + k4 * 4 + 2) =
        make_half2(__float2half_rn(__expf(-d2 * d2)), __float2half_rn(__expf(-d3 * d3)));
}

// ---------------- kernel 5: fp16 GEMM (m16n8k16), K = 4096, CTA 128x256 ----
// out[m][n] = sum_k acat[m][k] * bcat[n][k]
__global__ void __launch_bounds__(THREADS, 1)
k_gemm(float* __restrict__ out) {
    extern __shared__ char smem[];
    const uint32_t sbase = smem_u32(smem);
    const int tid  = threadIdx.x;
    const int warp = tid >> 5;
    const int lane = tid & 31;
    const int grp  = lane >> 2;   // 0..7
    const int tig  = lane & 3;    // 0..3
    const int warp_m = warp >> 2; // 0..1  (64-row slab)
    const int warp_n = warp & 3;  // 0..3  (64-col slab)

    const int m0 = blockIdx.y * BM;
    const int n0 = blockIdx.x * BN;

    const __half* ag = g_acat + (size_t)m0 * KTOT;
    const __half* bg = g_bcat + (size_t)n0 * KTOT;

    float acc[4][8][4];
    #pragma unroll
    for (int mi = 0; mi < 4; ++mi)
        #pragma unroll
        for (int ni = 0; ni < 8; ++ni)
            #pragma unroll
            for (int j = 0; j < 4; ++j) acc[mi][ni][j] = 0.f;

    // ldmatrix lane address components (all non-trans)
    // A x4: matrices (r0-7,k0-7),(r8-15,k0-7),(r0-7,k8-15),(r8-15,k8-15)
    const int rowA = warp_m * 64 + (lane & 7) + ((lane >> 3) & 1) * 8;
    const uint32_t colA = ((lane >> 4) & 1) * 16;
    // B x4: matrices (n0-7,k0-7),(n0-7,k8-15),(n8-15,k0-7),(n8-15,k8-15)
    const int rowB = warp_n * 64 + (lane & 7) + ((lane >> 4) & 1) * 8;
    const uint32_t colB = ((lane >> 3) & 1) * 16;

    // loader: A = 512 16B-chunks (2/thread), B = 1024 (4/thread)
    const int lrow = tid >> 2;        // 0..63, +64 per step
    const int lch  = tid & 3;         // 16B chunk within 64B k-row

    auto issue_stage = [&](int kc) {
        const int st = kc % STAGES;
        const uint32_t stA = sbase + (uint32_t)(st * STAGE_B);
        const uint32_t stB = stA + TILEA_B;
        const int k0 = kc * BK;
        #pragma unroll
        for (int i = 0; i < 2; ++i) {
            const int r = lrow + i * 64;
            cp16(stA + (uint32_t)(r * PITCH_B + lch * 16),
                 ag + (size_t)r * KTOT + k0 + lch * 8);
        }
        #pragma unroll
        for (int i = 0; i < 4; ++i) {
            const int r = lrow + i * 64;
            cp16(stB + (uint32_t)(r * PITCH_B + lch * 16),
                 bg + (size_t)r * KTOT + k0 + lch * 8);
        }
        CP_COMMIT();
    };

    // prologue: 5 stages in flight
    issue_stage(0);
    issue_stage(1);
    issue_stage(2);
    issue_stage(3);
    issue_stage(4);

    #pragma unroll 1
    for (int kc = 0; kc < NCHUNKS; ++kc) {
        CP_WAIT4();
        __syncthreads();

        if (kc + 5 < NCHUNKS) issue_stage(kc + 5);
        else CP_COMMIT();   // keep group accounting uniform

        const int st = kc % STAGES;
        const uint32_t stA = sbase + (uint32_t)(st * STAGE_B);
        const uint32_t stB = stA + TILEA_B;
        const uint32_t baseA = stA + (uint32_t)rowA * PITCH_B + colA;
        const uint32_t baseB = stB + (uint32_t)rowB * PITCH_B + colB;

        #pragma unroll
        for (int ks = 0; ks < 2; ++ks) {
            const uint32_t kb = (uint32_t)(ks * 32);

            uint32_t a[4][4];
            #pragma unroll
            for (int mi = 0; mi < 4; ++mi)
                ldsm_x4(a[mi][0], a[mi][1], a[mi][2], a[mi][3],
                        baseA + (uint32_t)(mi * 16 * PITCH_B) + kb);

            uint32_t b[8][2];
            #pragma unroll
            for (int np = 0; np < 4; ++np)
                ldsm_x4(b[2 * np][0], b[2 * np][1], b[2 * np + 1][0], b[2 * np + 1][1],
                        baseB + (uint32_t)(np * 16 * PITCH_B) + kb);

            #pragma unroll
            for (int mi = 0; mi < 4; ++mi)
                #pragma unroll
                for (int ni = 0; ni < 8; ++ni)
                    mma_f16(acc[mi][ni], a[mi][0], a[mi][1], a[mi][2], a[mi][3],
                            b[ni][0], b[ni][1]);
        }
        __syncthreads();
    }

    // ---- epilogue: direct float2 stores ----
    #pragma unroll
    for (int mi = 0; mi < 4; ++mi) {
        const int r = m0 + warp_m * 64 + mi * 16 + grp;
        #pragma unroll
        for (int ni = 0; ni < 8; ++ni) {
            const int c = n0 + warp_n * 64 + ni * 8 + tig * 2;
            float2 v0 = make_float2(acc[mi][ni][0], acc[mi][ni][1]);
            float2 v1 = make_float2(acc[mi][ni][2], acc[mi][ni][3]);
            *reinterpret_cast<float2*>(out + (size_t)r * OUT_F + c) = v0;
            *reinterpret_cast<float2*>(out + (size_t)(r + 8) * OUT_F + c) = v1;
        }
    }
}

// ---------------- launch ----------------
extern "C" void kernel_launch(void* const* d_in, const int* in_sizes, int n_in,
                              void* d_out, int out_size) {
    const float* x    = (const float*)d_in[0];
    const float* w1   = (const float*)d_in[1];
    const float* grid = (const float*)d_in[2];
    float* out = (float*)d_out;

    k_prep<<<dim3(OUT_F / 32, IN_F / 32), dim3(32, 32)>>>(grid);
    k_mean<<<1, 1024>>>();
    k_wcvt<<<(OUT_F * IN_F / 4) / 256, 256>>>(w1);
    k_xbasis<<<(BATCH * IN_F / 4) / 256, 256>>>(x);

    cudaFuncSetAttribute(k_gemm, cudaFuncAttributeMaxDynamicSharedMemorySize, SMEM_BYTES);
    k_gemm<<<dim3(OUT_F / BN, BATCH / BM), THREADS, SMEM_BYTES>>>(out);
}

// round 7
// speedup vs baseline: 2.2911x; 1.2289x over previous
#include <cuda_runtime.h>
#include <cuda_fp16.h>
#include <cstdint>

// ---------------- problem dims ----------------
#define IN_F   2048
#define OUT_F  2048
#define BATCH  8192
#define GDIM   8
#define KTOT   (2 * IN_F)          // 4096 concat K

// ---------------- GEMM config -----------------
#define BM      128
#define BN      128
#define BK      32                 // halves per chunk
#define STAGES  5
#define THREADS 256
#define NCHUNKS (KTOT / BK)        // 128
#define PITCH_B 80                 // bytes per smem row (40 halves, conflict-free)
#define TILEA_B (BM * PITCH_B)     // 10240 B
#define TILEB_B (BN * PITCH_B)     // 10240 B
#define STAGE_B (TILEA_B + TILEB_B)            // 20480 B
#define SMEM_BYTES (STAGES * STAGE_B)          // 102400

// ---------------- device scratch ----------------
__device__ __half g_acat[(size_t)BATCH * KTOT];  // [b][ x | basis ] fp16
__device__ __half g_bcat[(size_t)OUT_F * KTOT];  // [n][ w1 | gsumT ] fp16
__device__ float g_partials[4096];
__device__ float g_mean;

// ---------------- helpers ----------------
__device__ __forceinline__ uint32_t smem_u32(const void* p) {
    uint32_t a;
    asm("{ .reg .u64 t; cvta.to.shared.u64 t, %1; cvt.u32.u64 %0, t; }"
        : "=r"(a) : "l"(p));
    return a;
}

__device__ __forceinline__ void cp16(uint32_t dst, const void* src) {
    asm volatile("cp.async.cg.shared.global [%0], [%1], 16;"
                 :: "r"(dst), "l"(src));
}
#define CP_COMMIT() asm volatile("cp.async.commit_group;" ::: "memory")
#define CP_WAIT3()  asm volatile("cp.async.wait_group 3;" ::: "memory")

__device__ __forceinline__ void ldsm_x4(uint32_t& r0, uint32_t& r1,
                                        uint32_t& r2, uint32_t& r3, uint32_t addr) {
    asm volatile("ldmatrix.sync.aligned.m8n8.x4.shared.b16 {%0,%1,%2,%3}, [%4];"
                 : "=r"(r0), "=r"(r1), "=r"(r2), "=r"(r3) : "r"(addr));
}

__device__ __forceinline__ void mma_f16(float* c,
                                        uint32_t a0, uint32_t a1, uint32_t a2, uint32_t a3,
                                        uint32_t b0, uint32_t b1) {
    asm volatile(
        "mma.sync.aligned.m16n8k16.row.col.f32.f16.f16.f32 "
        "{%0,%1,%2,%3}, {%4,%5,%6,%7}, {%8,%9}, {%0,%1,%2,%3};"
        : "+f"(c[0]), "+f"(c[1]), "+f"(c[2]), "+f"(c[3])
        : "r"(a0), "r"(a1), "r"(a2), "r"(a3), "r"(b0), "r"(b1));
}

// ---------------- kernel 1: grid reduce + transpose into g_bcat + partials ----
__global__ void __launch_bounds__(1024) k_prep(const float* __restrict__ grid) {
    __shared__ float tile[32][33];
    __shared__ float wsum[32];
    int tx = threadIdx.x, ty = threadIdx.y;
    int i = blockIdx.y * 32 + ty;   // in-feature
    int o = blockIdx.x * 32 + tx;   // out-feature
    const float4* p = reinterpret_cast<const float4*>(grid + ((size_t)i * OUT_F + o) * GDIM);
    float4 a = p[0], b = p[1];
    float s = ((a.x + a.y) + (a.z + a.w)) + ((b.x + b.y) + (b.z + b.w));
    tile[ty][tx] = s;
    float r = s;
    #pragma unroll
    for (int off = 16; off > 0; off >>= 1)
        r += __shfl_xor_sync(0xFFFFFFFFu, r, off);
    if (tx == 0) wsum[ty] = r;
    __syncthreads();
    if (ty == 0) {
        float w = wsum[tx];
        #pragma unroll
        for (int off = 16; off > 0; off >>= 1)
            w += __shfl_xor_sync(0xFFFFFFFFu, w, off);
        if (tx == 0) g_partials[blockIdx.y * gridDim.x + blockIdx.x] = w;
    }
    // transposed fp16 write into concat-B upper half: bcat[o][2048 + i]
    float v = tile[tx][ty];
    int oo = blockIdx.x * 32 + ty;
    int ii = blockIdx.y * 32 + tx;
    g_bcat[(size_t)oo * KTOT + IN_F + ii] = __float2half_rn(v);
}

// ---------------- kernel 2: final mean ----------------
__global__ void __launch_bounds__(1024) k_mean() {
    __shared__ float red[1024];
    int t = threadIdx.x;
    red[t] = g_partials[t] + g_partials[t + 1024] + g_partials[t + 2048] + g_partials[t + 3072];
    __syncthreads();
    #pragma unroll
    for (int off = 512; off > 0; off >>= 1) {
        if (t < off) red[t] += red[t + off];
        __syncthreads();
    }
    if (t == 0) g_mean = red[0] * (1.0f / ((float)IN_F * (float)OUT_F * (float)GDIM));
}

// ---------------- kernel 3: w1 -> fp16 into g_bcat lower half ----------------
__global__ void __launch_bounds__(256) k_wcvt(const float* __restrict__ w1) {
    size_t idx = (size_t)blockIdx.x * 256 + threadIdx.x;   // float4 index
    const float4 f = reinterpret_cast<const float4*>(w1)[idx];
    size_t n = idx / (IN_F / 4);
    size_t k4 = idx % (IN_F / 4);
    __half2 h0 = make_half2(__float2half_rn(f.x), __float2half_rn(f.y));
    __half2 h1 = make_half2(__float2half_rn(f.z), __float2half_rn(f.w));
    *reinterpret_cast<__half2*>(g_bcat + n * KTOT + k4 * 4)     = h0;
    *reinterpret_cast<__half2*>(g_bcat + n * KTOT + k4 * 4 + 2) = h1;
}

// ---------------- kernel 4: x -> fp16 + basis -> g_acat ----------------
__global__ void __launch_bounds__(256) k_xbasis(const float* __restrict__ x) {
    const float gmean = g_mean;
    size_t idx = (size_t)blockIdx.x * 256 + threadIdx.x;   // float4 index
    const float4 f = reinterpret_cast<const float4*>(x)[idx];
    size_t b = idx / (IN_F / 4);
    size_t k4 = idx % (IN_F / 4);
    __half* dst = g_acat + b * KTOT;
    *reinterpret_cast<__half2*>(dst + k4 * 4) =
        make_half2(__float2half_rn(f.x), __float2half_rn(f.y));
    *reinterpret_cast<__half2*>(dst + k4 * 4 + 2) =
        make_half2(__float2half_rn(f.z), __float2half_rn(f.w));
    float d0 = f.x - gmean, d1 = f.y - gmean, d2 = f.z - gmean, d3 = f.w - gmean;
    *reinterpret_cast<__half2*>(dst + IN_F + k4 * 4) =
        make_half2(__float2half_rn(__expf(-d0 * d0)), __float2half_rn(__expf(-d1 * d1)));
    *reinterpret_cast<__half2*>(dst + IN_F + k4 * 4 + 2) =
        make_half2(__float2half_rn(__expf(-d2 * d2)), __float2half_rn(__expf(-d3 * d3)));
}

// ---------------- kernel 5: fp16 GEMM (m16n8k16), K = 4096, CTA 128x128 x2/SM ----
// out[m][n] = sum_k acat[m][k] * bcat[n][k]
__global__ void __launch_bounds__(THREADS, 2)
k_gemm(float* __restrict__ out) {
    extern __shared__ char smem[];
    const uint32_t sbase = smem_u32(smem);
    const int tid  = threadIdx.x;
    const int warp = tid >> 5;
    const int lane = tid & 31;
    const int grp  = lane >> 2;   // 0..7
    const int tig  = lane & 3;    // 0..3
    const int warp_m = warp >> 2; // 0..1  (64-row slab)
    const int warp_n = warp & 3;  // 0..3  (32-col slab)

    const int m0 = blockIdx.y * BM;
    const int n0 = blockIdx.x * BN;

    const __half* ag = g_acat + (size_t)m0 * KTOT;
    const __half* bg = g_bcat + (size_t)n0 * KTOT;

    float acc[4][4][4];
    #pragma unroll
    for (int mi = 0; mi < 4; ++mi)
        #pragma unroll
        for (int ni = 0; ni < 4; ++ni)
            #pragma unroll
            for (int j = 0; j < 4; ++j) acc[mi][ni][j] = 0.f;

    // ldmatrix lane address components (all non-trans)
    // A x4: matrices (r0-7,k0-7),(r8-15,k0-7),(r0-7,k8-15),(r8-15,k8-15)
    const int rowA = warp_m * 64 + (lane & 7) + ((lane >> 3) & 1) * 8;
    const uint32_t colA = ((lane >> 4) & 1) * 16;
    // B x4: matrices (n0-7,k0-7),(n0-7,k8-15),(n8-15,k0-7),(n8-15,k8-15)
    const int rowB = warp_n * 32 + (lane & 7) + ((lane >> 4) & 1) * 8;
    const uint32_t colB = ((lane >> 3) & 1) * 16;

    // loader: A = 512 16B-chunks (2/thread), B = 512 (2/thread)
    const int lrow = tid >> 2;        // 0..63, +64 per step
    const int lch  = tid & 3;         // 16B chunk within 64B k-row

    auto issue_stage = [&](int kc) {
        const int st = kc % STAGES;
        const uint32_t stA = sbase + (uint32_t)(st * STAGE_B);
        const uint32_t stB = stA + TILEA_B;
        const int k0 = kc * BK;
        #pragma unroll
        for (int i = 0; i < 2; ++i) {
            const int r = lrow + i * 64;
            cp16(stA + (uint32_t)(r * PITCH_B + lch * 16),
                 ag + (size_t)r * KTOT + k0 + lch * 8);
            cp16(stB + (uint32_t)(r * PITCH_B + lch * 16),
                 bg + (size_t)r * KTOT + k0 + lch * 8);
        }
        CP_COMMIT();
    };

    // prologue: 4 stages in flight
    issue_stage(0);
    issue_stage(1);
    issue_stage(2);
    issue_stage(3);

    #pragma unroll 1
    for (int kc = 0; kc < NCHUNKS; ++kc) {
        CP_WAIT3();
        __syncthreads();

        if (kc + 4 < NCHUNKS) issue_stage(kc + 4);
        else CP_COMMIT();   // keep group accounting uniform

        const int st = kc % STAGES;
        const uint32_t stA = sbase + (uint32_t)(st * STAGE_B);
        const uint32_t stB = stA + TILEA_B;
        const uint32_t baseA = stA + (uint32_t)rowA * PITCH_B + colA;
        const uint32_t baseB = stB + (uint32_t)rowB * PITCH_B + colB;

        #pragma unroll
        for (int ks = 0; ks < 2; ++ks) {
            const uint32_t kb = (uint32_t)(ks * 32);

            uint32_t a[4][4];
            #pragma unroll
            for (int mi = 0; mi < 4; ++mi)
                ldsm_x4(a[mi][0], a[mi][1], a[mi][2], a[mi][3],
                        baseA + (uint32_t)(mi * 16 * PITCH_B) + kb);

            uint32_t b[4][2];
            #pragma unroll
            for (int np = 0; np < 2; ++np)
                ldsm_x4(b[2 * np][0], b[2 * np][1], b[2 * np + 1][0], b[2 * np + 1][1],
                        baseB + (uint32_t)(np * 16 * PITCH_B) + kb);

            #pragma unroll
            for (int mi = 0; mi < 4; ++mi)
                #pragma unroll
                for (int ni = 0; ni < 4; ++ni)
                    mma_f16(acc[mi][ni], a[mi][0], a[mi][1], a[mi][2], a[mi][3],
                            b[ni][0], b[ni][1]);
        }
        __syncthreads();
    }

    // ---- epilogue: direct float2 stores ----
    #pragma unroll
    for (int mi = 0; mi < 4; ++mi) {
        const int r = m0 + warp_m * 64 + mi * 16 + grp;
        #pragma unroll
        for (int ni = 0; ni < 4; ++ni) {
            const int c = n0 + warp_n * 32 + ni * 8 + tig * 2;
            float2 v0 = make_float2(acc[mi][ni][0], acc[mi][ni][1]);
            float2 v1 = make_float2(acc[mi][ni][2], acc[mi][ni][3]);
            *reinterpret_cast<float2*>(out + (size_t)r * OUT_F + c) = v0;
            *reinterpret_cast<float2*>(out + (size_t)(r + 8) * OUT_F + c) = v1;
        }
    }
}

// ---------------- launch ----------------
extern "C" void kernel_launch(void* const* d_in, const int* in_sizes, int n_in,
                              void* d_out, int out_size) {
    const float* x    = (const float*)d_in[0];
    const float* w1   = (const float*)d_in[1];
    const float* grid = (const float*)d_in[2];
    float* out = (float*)d_out;

    k_prep<<<dim3(OUT_F / 32, IN_F / 32), dim3(32, 32)>>>(grid);
    k_mean<<<1, 1024>>>();
    k_wcvt<<<(OUT_F * IN_F / 4) / 256, 256>>>(w1);
    k_xbasis<<<(BATCH * IN_F / 4) / 256, 256>>>(x);

    cudaFuncSetAttribute(k_gemm, cudaFuncAttributeMaxDynamicSharedMemorySize, SMEM_BYTES);
    k_gemm<<<dim3(OUT_F / BN, BATCH / BM), THREADS, SMEM_BYTES>>>(out);
}

// round 8
// speedup vs baseline: 2.5622x; 1.1183x over previous
#include <cuda_runtime.h>
#include <cuda_fp16.h>
#include <cstdint>

// ---------------- problem dims ----------------
#define IN_F   2048
#define OUT_F  2048
#define BATCH  8192
#define GDIM   8
#define KTOT   (2 * IN_F)          // 4096 concat K

// ---------------- GEMM config -----------------
#define BM      128
#define BN      128
#define BK      32                 // halves per chunk
#define STAGES  5
#define THREADS 128                // 4 warps, 2x2 grid of 64x64 warp tiles
#define NCHUNKS (KTOT / BK)        // 128
#define PITCH_B 80                 // bytes per smem row (40 halves, conflict-free)
#define TILEA_B (BM * PITCH_B)     // 10240 B
#define TILEB_B (BN * PITCH_B)     // 10240 B
#define STAGE_B (TILEA_B + TILEB_B)            // 20480 B
#define SMEM_BYTES (STAGES * STAGE_B)          // 102400

// ---------------- device scratch ----------------
__device__ __half g_acat[(size_t)BATCH * KTOT];  // [b][ x | basis ] fp16
__device__ __half g_bcat[(size_t)OUT_F * KTOT];  // [n][ w1 | gsumT ] fp16
__device__ float g_partials[4096];
__device__ float g_mean;

// ---------------- helpers ----------------
__device__ __forceinline__ uint32_t smem_u32(const void* p) {
    uint32_t a;
    asm("{ .reg .u64 t; cvta.to.shared.u64 t, %1; cvt.u32.u64 %0, t; }"
        : "=r"(a) : "l"(p));
    return a;
}

__device__ __forceinline__ void cp16(uint32_t dst, const void* src) {
    asm volatile("cp.async.cg.shared.global [%0], [%1], 16;"
                 :: "r"(dst), "l"(src));
}
#define CP_COMMIT() asm volatile("cp.async.commit_group;" ::: "memory")
#define CP_WAIT3()  asm volatile("cp.async.wait_group 3;" ::: "memory")

__device__ __forceinline__ void ldsm_x4(uint32_t& r0, uint32_t& r1,
                                        uint32_t& r2, uint32_t& r3, uint32_t addr) {
    asm volatile("ldmatrix.sync.aligned.m8n8.x4.shared.b16 {%0,%1,%2,%3}, [%4];"
                 : "=r"(r0), "=r"(r1), "=r"(r2), "=r"(r3) : "r"(addr));
}

__device__ __forceinline__ void mma_f16(float* c,
                                        uint32_t a0, uint32_t a1, uint32_t a2, uint32_t a3,
                                        uint32_t b0, uint32_t b1) {
    asm volatile(
        "mma.sync.aligned.m16n8k16.row.col.f32.f16.f16.f32 "
        "{%0,%1,%2,%3}, {%4,%5,%6,%7}, {%8,%9}, {%0,%1,%2,%3};"
        : "+f"(c[0]), "+f"(c[1]), "+f"(c[2]), "+f"(c[3])
        : "r"(a0), "r"(a1), "r"(a2), "r"(a3), "r"(b0), "r"(b1));
}

// ---------------- kernel 1: grid reduce + transpose into g_bcat + partials ----
__global__ void __launch_bounds__(1024) k_prep(const float* __restrict__ grid) {
    __shared__ float tile[32][33];
    __shared__ float wsum[32];
    int tx = threadIdx.x, ty = threadIdx.y;
    int i = blockIdx.y * 32 + ty;   // in-feature
    int o = blockIdx.x * 32 + tx;   // out-feature
    const float4* p = reinterpret_cast<const float4*>(grid + ((size_t)i * OUT_F + o) * GDIM);
    float4 a = p[0], b = p[1];
    float s = ((a.x + a.y) + (a.z + a.w)) + ((b.x + b.y) + (b.z + b.w));
    tile[ty][tx] = s;
    float r = s;
    #pragma unroll
    for (int off = 16; off > 0; off >>= 1)
        r += __shfl_xor_sync(0xFFFFFFFFu, r, off);
    if (tx == 0) wsum[ty] = r;
    __syncthreads();
    if (ty == 0) {
        float w = wsum[tx];
        #pragma unroll
        for (int off = 16; off > 0; off >>= 1)
            w += __shfl_xor_sync(0xFFFFFFFFu, w, off);
        if (tx == 0) g_partials[blockIdx.y * gridDim.x + blockIdx.x] = w;
    }
    // transposed fp16 write into concat-B upper half: bcat[o][2048 + i]
    float v = tile[tx][ty];
    int oo = blockIdx.x * 32 + ty;
    int ii = blockIdx.y * 32 + tx;
    g_bcat[(size_t)oo * KTOT + IN_F + ii] = __float2half_rn(v);
}

// ---------------- kernel 2: final mean ----------------
__global__ void __launch_bounds__(1024) k_mean() {
    __shared__ float red[1024];
    int t = threadIdx.x;
    red[t] = g_partials[t] + g_partials[t + 1024] + g_partials[t + 2048] + g_partials[t + 3072];
    __syncthreads();
    #pragma unroll
    for (int off = 512; off > 0; off >>= 1) {
        if (t < off) red[t] += red[t + off];
        __syncthreads();
    }
    if (t == 0) g_mean = red[0] * (1.0f / ((float)IN_F * (float)OUT_F * (float)GDIM));
}

// ---------------- kernel 3: w1 -> fp16 into g_bcat lower half ----------------
__global__ void __launch_bounds__(256) k_wcvt(const float* __restrict__ w1) {
    size_t idx = (size_t)blockIdx.x * 256 + threadIdx.x;   // float4 index
    const float4 f = reinterpret_cast<const float4*>(w1)[idx];
    size_t n = idx / (IN_F / 4);
    size_t k4 = idx % (IN_F / 4);
    __half2 h0 = make_half2(__float2half_rn(f.x), __float2half_rn(f.y));
    __half2 h1 = make_half2(__float2half_rn(f.z), __float2half_rn(f.w));
    *reinterpret_cast<__half2*>(g_bcat + n * KTOT + k4 * 4)     = h0;
    *reinterpret_cast<__half2*>(g_bcat + n * KTOT + k4 * 4 + 2) = h1;
}

// ---------------- kernel 4: x -> fp16 + basis -> g_acat ----------------
__global__ void __launch_bounds__(256) k_xbasis(const float* __restrict__ x) {
    const float gmean = g_mean;
    size_t idx = (size_t)blockIdx.x * 256 + threadIdx.x;   // float4 index
    const float4 f = reinterpret_cast<const float4*>(x)[idx];
    size_t b = idx / (IN_F / 4);
    size_t k4 = idx % (IN_F / 4);
    __half* dst = g_acat + b * KTOT;
    *reinterpret_cast<__half2*>(dst + k4 * 4) =
        make_half2(__float2half_rn(f.x), __float2half_rn(f.y));
    *reinterpret_cast<__half2*>(dst + k4 * 4 + 2) =
        make_half2(__float2half_rn(f.z), __float2half_rn(f.w));
    float d0 = f.x - gmean, d1 = f.y - gmean, d2 = f.z - gmean, d3 = f.w - gmean;
    *reinterpret_cast<__half2*>(dst + IN_F + k4 * 4) =
        make_half2(__float2half_rn(__expf(-d0 * d0)), __float2half_rn(__expf(-d1 * d1)));
    *reinterpret_cast<__half2*>(dst + IN_F + k4 * 4 + 2) =
        make_half2(__float2half_rn(__expf(-d2 * d2)), __float2half_rn(__expf(-d3 * d3)));
}

// ---------------- kernel 5: fp16 GEMM, CTA 128x128, 4 warps of 64x64, x2/SM ----
// out[m][n] = sum_k acat[m][k] * bcat[n][k]
__global__ void __launch_bounds__(THREADS, 2)
k_gemm(float* __restrict__ out) {
    extern __shared__ char smem[];
    const uint32_t sbase = smem_u32(smem);
    const int tid  = threadIdx.x;
    const int warp = tid >> 5;
    const int lane = tid & 31;
    const int grp  = lane >> 2;   // 0..7
    const int tig  = lane & 3;    // 0..3
    const int warp_m = warp >> 1; // 0..1  (64-row slab)
    const int warp_n = warp & 1;  // 0..1  (64-col slab)

    const int m0 = blockIdx.y * BM;
    const int n0 = blockIdx.x * BN;

    const __half* ag = g_acat + (size_t)m0 * KTOT;
    const __half* bg = g_bcat + (size_t)n0 * KTOT;

    float acc[4][8][4];
    #pragma unroll
    for (int mi = 0; mi < 4; ++mi)
        #pragma unroll
        for (int ni = 0; ni < 8; ++ni)
            #pragma unroll
            for (int j = 0; j < 4; ++j) acc[mi][ni][j] = 0.f;

    // ldmatrix lane address components (all non-trans)
    // A x4: matrices (r0-7,k0-7),(r8-15,k0-7),(r0-7,k8-15),(r8-15,k8-15)
    const int rowA = warp_m * 64 + (lane & 7) + ((lane >> 3) & 1) * 8;
    const uint32_t colA = ((lane >> 4) & 1) * 16;
    // B x4: matrices (n0-7,k0-7),(n0-7,k8-15),(n8-15,k0-7),(n8-15,k8-15)
    const int rowB = warp_n * 64 + (lane & 7) + ((lane >> 4) & 1) * 8;
    const uint32_t colB = ((lane >> 3) & 1) * 16;

    // loader: A = 512 16B-chunks (4/thread), B = 512 (4/thread); 128 threads
    const int lrow = tid >> 2;        // 0..31, +32 per step
    const int lch  = tid & 3;         // 16B chunk within 64B k-row

    auto issue_stage = [&](int kc) {
        const int st = kc % STAGES;
        const uint32_t stA = sbase + (uint32_t)(st * STAGE_B);
        const uint32_t stB = stA + TILEA_B;
        const int k0 = kc * BK;
        #pragma unroll
        for (int i = 0; i < 4; ++i) {
            const int r = lrow + i * 32;
            cp16(stA + (uint32_t)(r * PITCH_B + lch * 16),
                 ag + (size_t)r * KTOT + k0 + lch * 8);
            cp16(stB + (uint32_t)(r * PITCH_B + lch * 16),
                 bg + (size_t)r * KTOT + k0 + lch * 8);
        }
        CP_COMMIT();
    };

    // prologue: 4 stages in flight
    issue_stage(0);
    issue_stage(1);
    issue_stage(2);
    issue_stage(3);

    #pragma unroll 1
    for (int kc = 0; kc < NCHUNKS; ++kc) {
        CP_WAIT3();
        __syncthreads();

        if (kc + 4 < NCHUNKS) issue_stage(kc + 4);
        else CP_COMMIT();   // keep group accounting uniform

        const int st = kc % STAGES;
        const uint32_t stA = sbase + (uint32_t)(st * STAGE_B);
        const uint32_t stB = stA + TILEA_B;
        const uint32_t baseA = stA + (uint32_t)rowA * PITCH_B + colA;
        const uint32_t baseB = stB + (uint32_t)rowB * PITCH_B + colB;

        #pragma unroll
        for (int ks = 0; ks < 2; ++ks) {
            const uint32_t kb = (uint32_t)(ks * 32);

            uint32_t a[4][4];
            #pragma unroll
            for (int mi = 0; mi < 4; ++mi)
                ldsm_x4(a[mi][0], a[mi][1], a[mi][2], a[mi][3],
                        baseA + (uint32_t)(mi * 16 * PITCH_B) + kb);

            uint32_t b[8][2];
            #pragma unroll
            for (int np = 0; np < 4; ++np)
                ldsm_x4(b[2 * np][0], b[2 * np][1], b[2 * np + 1][0], b[2 * np + 1][1],
                        baseB + (uint32_t)(np * 16 * PITCH_B) + kb);

            #pragma unroll
            for (int mi = 0; mi < 4; ++mi)
                #pragma unroll
                for (int ni = 0; ni < 8; ++ni)
                    mma_f16(acc[mi][ni], a[mi][0], a[mi][1], a[mi][2], a[mi][3],
                            b[ni][0], b[ni][1]);
        }
        __syncthreads();
    }

    // ---- epilogue: direct float2 stores ----
    #pragma unroll
    for (int mi = 0; mi < 4; ++mi) {
        const int r = m0 + warp_m * 64 + mi * 16 + grp;
        #pragma unroll
        for (int ni = 0; ni < 8; ++ni) {
            const int c = n0 + warp_n * 64 + ni * 8 + tig * 2;
            float2 v0 = make_float2(acc[mi][ni][0], acc[mi][ni][1]);
            float2 v1 = make_float2(acc[mi][ni][2], acc[mi][ni][3]);
            *reinterpret_cast<float2*>(out + (size_t)r * OUT_F + c) = v0;
            *reinterpret_cast<float2*>(out + (size_t)(r + 8) * OUT_F + c) = v1;
        }
    }
}

// ---------------- launch ----------------
extern "C" void kernel_launch(void* const* d_in, const int* in_sizes, int n_in,
                              void* d_out, int out_size) {
    const float* x    = (const float*)d_in[0];
    const float* w1   = (const float*)d_in[1];
    const float* grid = (const float*)d_in[2];
    float* out = (float*)d_out;

    k_prep<<<dim3(OUT_F / 32, IN_F / 32), dim3(32, 32)>>>(grid);
    k_mean<<<1, 1024>>>();
    k_wcvt<<<(OUT_F * IN_F / 4) / 256, 256>>>(w1);
    k_xbasis<<<(BATCH * IN_F / 4) / 256, 256>>>(x);

    cudaFuncSetAttribute(k_gemm, cudaFuncAttributeMaxDynamicSharedMemorySize, SMEM_BYTES);
    k_gemm<<<dim3(OUT_F / BN, BATCH / BM), THREADS, SMEM_BYTES>>>(out);
}

// round 11
// speedup vs baseline: 2.5792x; 1.0066x over previous
#include <cuda_runtime.h>
#include <cuda_fp16.h>
#include <cstdint>

// ---------------- problem dims ----------------
#define IN_F   2048
#define OUT_F  2048
#define BATCH  8192
#define GDIM   8
#define KTOT   (2 * IN_F)          // 4096 concat K

// ---------------- GEMM config -----------------
#define BM      128
#define BN      128
#define BK      64                 // halves per chunk (128 B per row)
#define STAGES  3
#define THREADS 128                // 4 warps, 2x2 grid of 64x64 warp tiles
#define NCHUNKS (KTOT / BK)        // 64
#define PITCH_B 144                // bytes per smem row (128 data + 16 pad)
#define TILE_B  (BM * PITCH_B)     // 18432 B per operand tile
#define STAGE_B (2 * TILE_B)       // 36864 B
#define SMEM_BYTES (STAGES * STAGE_B)          // 110592

// ---------------- device scratch ----------------
__device__ __half g_acat[(size_t)BATCH * KTOT];  // [b][ x | basis ] fp16
__device__ __half g_bcat[(size_t)OUT_F * KTOT];  // [n][ w1 | gsumT ] fp16
__device__ float g_partials[4096];
__device__ float g_mean;

// ---------------- helpers ----------------
__device__ __forceinline__ uint32_t smem_u32(const void* p) {
    uint32_t a;
    asm("{ .reg .u64 t; cvta.to.shared.u64 t, %1; cvt.u32.u64 %0, t; }"
        : "=r"(a) : "l"(p));
    return a;
}

__device__ __forceinline__ void cp16(uint32_t dst, const void* src) {
    asm volatile("cp.async.cg.shared.global [%0], [%1], 16;"
                 :: "r"(dst), "l"(src));
}
#define CP_COMMIT() asm volatile("cp.async.commit_group;" ::: "memory")
#define CP_WAIT1()  asm volatile("cp.async.wait_group 1;" ::: "memory")

__device__ __forceinline__ void ldsm_x4(uint32_t& r0, uint32_t& r1,
                                        uint32_t& r2, uint32_t& r3, uint32_t addr) {
    asm volatile("ldmatrix.sync.aligned.m8n8.x4.shared.b16 {%0,%1,%2,%3}, [%4];"
                 : "=r"(r0), "=r"(r1), "=r"(r2), "=r"(r3) : "r"(addr));
}

__device__ __forceinline__ void mma_f16(float* c,
                                        uint32_t a0, uint32_t a1, uint32_t a2, uint32_t a3,
                                        uint32_t b0, uint32_t b1) {
    asm volatile(
        "mma.sync.aligned.m16n8k16.row.col.f32.f16.f16.f32 "
        "{%0,%1,%2,%3}, {%4,%5,%6,%7}, {%8,%9}, {%0,%1,%2,%3};"
        : "+f"(c[0]), "+f"(c[1]), "+f"(c[2]), "+f"(c[3])
        : "r"(a0), "r"(a1), "r"(a2), "r"(a3), "r"(b0), "r"(b1));
}

// ---------------- kernel 1: grid reduce + transpose into g_bcat + partials ----
__global__ void __launch_bounds__(1024) k_prep(const float* __restrict__ grid) {
    __shared__ float tile[32][33];
    __shared__ float wsum[32];
    int tx = threadIdx.x, ty = threadIdx.y;
    int i = blockIdx.y * 32 + ty;   // in-feature
    int o = blockIdx.x * 32 + tx;   // out-feature
    const float4* p = reinterpret_cast<const float4*>(grid + ((size_t)i * OUT_F + o) * GDIM);
    float4 a = p[0], b = p[1];
    float s = ((a.x + a.y) + (a.z + a.w)) + ((b.x + b.y) + (b.z + b.w));
    tile[ty][tx] = s;
    float r = s;
    #pragma unroll
    for (int off = 16; off > 0; off >>= 1)
        r += __shfl_xor_sync(0xFFFFFFFFu, r, off);
    if (tx == 0) wsum[ty] = r;
    __syncthreads();
    if (ty == 0) {
        float w = wsum[tx];
        #pragma unroll
        for (int off = 16; off > 0; off >>= 1)
            w += __shfl_xor_sync(0xFFFFFFFFu, w, off);
        if (tx == 0) g_partials[blockIdx.y * gridDim.x + blockIdx.x] = w;
    }
    // transposed fp16 write into concat-B upper half: bcat[o][2048 + i]
    float v = tile[tx][ty];
    int oo = blockIdx.x * 32 + ty;
    int ii = blockIdx.y * 32 + tx;
    g_bcat[(size_t)oo * KTOT + IN_F + ii] = __float2half_rn(v);
}

// ---------------- kernel 2: final mean ----------------
__global__ void __launch_bounds__(1024) k_mean() {
    __shared__ float red[1024];
    int t = threadIdx.x;
    red[t] = g_partials[t] + g_partials[t + 1024] + g_partials[t + 2048] + g_partials[t + 3072];
    __syncthreads();
    #pragma unroll
    for (int off = 512; off > 0; off >>= 1) {
        if (t < off) red[t] += red[t + off];
        __syncthreads();
    }
    if (t == 0) g_mean = red[0] * (1.0f / ((float)IN_F * (float)OUT_F * (float)GDIM));
}

// ---------------- kernel 3: w1 -> fp16 into g_bcat lower half ----------------
__global__ void __launch_bounds__(256) k_wcvt(const float* __restrict__ w1) {
    size_t idx = (size_t)blockIdx.x * 256 + threadIdx.x;   // float4 index
    const float4 f = reinterpret_cast<const float4*>(w1)[idx];
    size_t n = idx / (IN_F / 4);
    size_t k4 = idx % (IN_F / 4);
    __half2 h0 = make_half2(__float2half_rn(f.x), __float2half_rn(f.y));
    __half2 h1 = make_half2(__float2half_rn(f.z), __float2half_rn(f.w));
    *reinterpret_cast<__half2*>(g_bcat + n * KTOT + k4 * 4)     = h0;
    *reinterpret_cast<__half2*>(g_bcat + n * KTOT + k4 * 4 + 2) = h1;
}

// ---------------- kernel 4: x -> fp16 + basis -> g_acat ----------------
__global__ void __launch_bounds__(256) k_xbasis(const float* __restrict__ x) {
    const float gmean = g_mean;
    size_t idx = (size_t)blockIdx.x * 256 + threadIdx.x;   // float4 index
    const float4 f = reinterpret_cast<const float4*>(x)[idx];
    size_t b = idx / (IN_F / 4);
    size_t k4 = idx % (IN_F / 4);
    __half* dst = g_acat + b * KTOT;
    *reinterpret_cast<__half2*>(dst + k4 * 4) =
        make_half2(__float2half_rn(f.x), __float2half_rn(f.y));
    *reinterpret_cast<__half2*>(dst + k4 * 4 + 2) =
        make_half2(__float2half_rn(f.z), __float2half_rn(f.w));
    float d0 = f.x - gmean, d1 = f.y - gmean, d2 = f.z - gmean, d3 = f.w - gmean;
    *reinterpret_cast<__half2*>(dst + IN_F + k4 * 4) =
        make_half2(__float2half_rn(__expf(-d0 * d0)), __float2half_rn(__expf(-d1 * d1)));
    *reinterpret_cast<__half2*>(dst + IN_F + k4 * 4 + 2) =
        make_half2(__float2half_rn(__expf(-d2 * d2)), __float2half_rn(__expf(-d3 * d3)));
}

// ---------------- kernel 5: fp16 GEMM, CTA 128x128, 4 warps of 64x64, x2/SM ----
// out[m][n] = sum_k acat[m][k] * bcat[n][k]
__global__ void __launch_bounds__(THREADS, 2)
k_gemm(float* __restrict__ out) {
    extern __shared__ char smem[];
    const uint32_t sbase = smem_u32(smem);
    const int tid  = threadIdx.x;
    const int warp = tid >> 5;
    const int lane = tid & 31;
    const int grp  = lane >> 2;   // 0..7
    const int tig  = lane & 3;    // 0..3
    const int warp_m = warp >> 1; // 0..1  (64-row slab)
    const int warp_n = warp & 1;  // 0..1  (64-col slab)

    const int m0 = blockIdx.y * BM;
    const int n0 = blockIdx.x * BN;

    const __half* ag = g_acat + (size_t)m0 * KTOT;
    const __half* bg = g_bcat + (size_t)n0 * KTOT;

    float acc[4][8][4];
    #pragma unroll
    for (int mi = 0; mi < 4; ++mi)
        #pragma unroll
        for (int ni = 0; ni < 8; ++ni)
            #pragma unroll
            for (int j = 0; j < 4; ++j) acc[mi][ni][j] = 0.f;

    // ldmatrix lane address components (all non-trans)
    const int rowA = warp_m * 64 + (lane & 7) + ((lane >> 3) & 1) * 8;
    const uint32_t colA = ((lane >> 4) & 1) * 16;
    const int rowB = warp_n * 64 + (lane & 7) + ((lane >> 4) & 1) * 8;
    const uint32_t colB = ((lane >> 3) & 1) * 16;

    // loader: per tile 128 rows x 8 chunks(16B) = 1024; 8 per thread per tile
    const int lrow = tid >> 3;        // 0..15, +16 per step
    const int lch  = tid & 7;         // 16B chunk within 128B row

    auto issue_stage = [&](int kc) {
        const int st = kc % STAGES;
        const uint32_t stA = sbase + (uint32_t)(st * STAGE_B);
        const uint32_t stB = stA + TILE_B;
        const int k0 = kc * BK;
        #pragma unroll
        for (int i = 0; i < 8; ++i) {
            const int r = lrow + i * 16;
            cp16(stA + (uint32_t)(r * PITCH_B + lch * 16),
                 ag + (size_t)r * KTOT + k0 + lch * 8);
            cp16(stB + (uint32_t)(r * PITCH_B + lch * 16),
                 bg + (size_t)r * KTOT + k0 + lch * 8);
        }
        CP_COMMIT();
    };

    // prologue: 2 stages in flight
    issue_stage(0);
    issue_stage(1);

    #pragma unroll 1
    for (int kc = 0; kc < NCHUNKS; ++kc) {
        CP_WAIT1();
        __syncthreads();

        if (kc + 2 < NCHUNKS) issue_stage(kc + 2);
        else CP_COMMIT();   // keep group accounting uniform

        const int st = kc % STAGES;
        const uint32_t stA = sbase + (uint32_t)(st * STAGE_B);
        const uint32_t stB = stA + TILE_B;
        const uint32_t baseA = stA + (uint32_t)rowA * PITCH_B + colA;
        const uint32_t baseB = stB + (uint32_t)rowB * PITCH_B + colB;

        // 4 k16-slices per chunk, fragment double-buffered
        uint32_t a[2][4][4], b[2][8][2];

        // load slice 0 into buf 0
        #pragma unroll
        for (int mi = 0; mi < 4; ++mi)
            ldsm_x4(a[0][mi][0], a[0][mi][1], a[0][mi][2], a[0][mi][3],
                    baseA + (uint32_t)(mi * 16 * PITCH_B));
        #pragma unroll
        for (int np = 0; np < 4; ++np)
            ldsm_x4(b[0][2 * np][0], b[0][2 * np][1], b[0][2 * np + 1][0], b[0][2 * np + 1][1],
                    baseB + (uint32_t)(np * 16 * PITCH_B));

        #pragma unroll
        for (int ks = 0; ks < 4; ++ks) {
            const int cur = ks & 1;
            const int nxt = cur ^ 1;
            if (ks < 3) {
                const uint32_t kb = (uint32_t)((ks + 1) * 32);
                #pragma unroll
                for (int mi = 0; mi < 4; ++mi)
                    ldsm_x4(a[nxt][mi][0], a[nxt][mi][1], a[nxt][mi][2], a[nxt][mi][3],
                            baseA + (uint32_t)(mi * 16 * PITCH_B) + kb);
                #pragma unroll
                for (int np = 0; np < 4; ++np)
                    ldsm_x4(b[nxt][2 * np][0], b[nxt][2 * np][1],
                            b[nxt][2 * np + 1][0], b[nxt][2 * np + 1][1],
                            baseB + (uint32_t)(np * 16 * PITCH_B) + kb);
            }
            #pragma unroll
            for (int mi = 0; mi < 4; ++mi)
                #pragma unroll
                for (int ni = 0; ni < 8; ++ni)
                    mma_f16(acc[mi][ni], a[cur][mi][0], a[cur][mi][1],
                            a[cur][mi][2], a[cur][mi][3],
                            b[cur][ni][0], b[cur][ni][1]);
        }
    }

    // ---- epilogue: direct float2 stores ----
    #pragma unroll
    for (int mi = 0; mi < 4; ++mi) {
        const int r = m0 + warp_m * 64 + mi * 16 + grp;
        #pragma unroll
        for (int ni = 0; ni < 8; ++ni) {
            const int c = n0 + warp_n * 64 + ni * 8 + tig * 2;
            float2 v0 = make_float2(acc[mi][ni][0], acc[mi][ni][1]);
            float2 v1 = make_float2(acc[mi][ni][2], acc[mi][ni][3]);
            *reinterpret_cast<float2*>(out + (size_t)r * OUT_F + c) = v0;
            *reinterpret_cast<float2*>(out + (size_t)(r + 8) * OUT_F + c) = v1;
        }
    }
}

// ---------------- launch ----------------
extern "C" void kernel_launch(void* const* d_in, const int* in_sizes, int n_in,
                              void* d_out, int out_size) {
    const float* x    = (const float*)d_in[0];
    const float* w1   = (const float*)d_in[1];
    const float* grid = (const float*)d_in[2];
    float* out = (float*)d_out;

    k_prep<<<dim3(OUT_F / 32, IN_F / 32), dim3(32, 32)>>>(grid);
    k_mean<<<1, 1024>>>();
    k_wcvt<<<(OUT_F * IN_F / 4) / 256, 256>>>(w1);
    k_xbasis<<<(BATCH * IN_F / 4) / 256, 256>>>(x);

    cudaFuncSetAttribute(k_gemm, cudaFuncAttributeMaxDynamicSharedMemorySize, SMEM_BYTES);
    k_gemm<<<dim3(OUT_F / BN, BATCH / BM), THREADS, SMEM_BYTES>>>(out);
}